// round 13
// baseline (speedup 1.0000x reference)
#include <cuda_runtime.h>
#include <math.h>
#include <stdint.h>

#define DD 1024
#define BB 32
#define SS 512
#define NCOL 8          // columns per block (warp per column)
#define NBLK 128        // 128*8 = 1024 columns
#define NTHR 256        // 8 warps
#define HK 512          // kc panel (Eigen join boundary)
#define XPAD 516        // panel row stride (conflict-free LDS.128)

__device__ float g_h0all[(size_t)SS * BB * DD];  // layer-0 out, [S][B][D]
__device__ float g_h[2][BB * DD];                // recurrent state, [B][D]
__device__ unsigned g_done[2];

// ---- lockstep sync (validated) ----
__device__ __forceinline__ unsigned ld_acq(const unsigned* p) {
    unsigned v;
    asm volatile("ld.acquire.gpu.global.u32 %0, [%1];" : "=r"(v) : "l"(p) : "memory");
    return v;
}
__device__ __forceinline__ void red_release_add(unsigned* p) {
    asm volatile("red.release.gpu.global.add.u32 [%0], %1;" :: "l"(p), "r"(1u) : "memory");
}
__device__ __forceinline__ void wait_ge(const unsigned* ctr, unsigned target) {
    if (threadIdx.x == 0) { while (ld_acq(ctr) < target) { } }
    __syncthreads();
}

// ---- XLA EmitFastTanh, with_fma=true: clamp 7.99881172180175781, fma Horner ----
__device__ __forceinline__ float xla_tanh_fma(float x) {
    const float kMax = 7.99881172180175781f;
    float tc = fmaxf(fminf(x, kMax), -kMax);
    float x2 = __fmul_rn(tc, tc);
    float p;
    p = fmaf(x2, -2.76076847742355e-16f, 2.00018790482477e-13f);
    p = fmaf(x2, p, -8.60467152213735e-11f);
    p = fmaf(x2, p,  5.12229709037114e-08f);
    p = fmaf(x2, p,  1.48572235717979e-05f);
    p = fmaf(x2, p,  6.37261928875436e-04f);
    p = fmaf(x2, p,  4.89352455891786e-03f);
    p = __fmul_rn(tc, p);
    float q;
    q = fmaf(x2, 1.19825839466702e-06f, 1.18534705686654e-04f);
    q = fmaf(x2, q, 2.26843463243900e-03f);
    q = fmaf(x2, q, 4.89352518554385e-03f);
    float r = __fdiv_rn(p, q);
    return (fabsf(x) < 0.0004f) ? x : r;
}

__global__ void init_kernel() { g_done[0] = 0u; g_done[1] = 0u; }

// One layer, 512 lockstep steps.
// Per output (b, n): ax = seq-fma chain k=0..511, joined (+) chain k=512..1023;
// same for ah; pre = (ax + ah) + bias; out = XLA fma-tanh.  [= R12 cell c2, bit-exact]
__global__ void __launch_bounds__(NTHR, 1) rnn_layer(
    const float* __restrict__ in, size_t in_st_t, size_t in_st_b,  // in[t*st_t + b*st_b + k]
    const float* __restrict__ W,      // [D][D] k-major
    const float* __restrict__ U,
    const float* __restrict__ bias_l, // [D]
    float* __restrict__ outp, size_t out_st_t, size_t out_st_b,
    int ctr_idx)
{
    extern __shared__ float smem[];
    float* Wsh  = smem;                         // [NCOL][DD]
    float* Ush  = smem + NCOL * DD;             // [NCOL][DD]
    float* xpan = smem + 2 * NCOL * DD;         // [BB][XPAD] half-k panel of x
    float* hpan = xpan + BB * XPAD;             // [BB][XPAD] half-k panel of h
    __shared__ float red[NCOL * 33];

    const int nb  = blockIdx.x * NCOL;
    const int tid = threadIdx.x;
    unsigned* ctr = &g_done[ctr_idx];

    // weight columns -> SMEM (once): Wsh[j][k] = W[k][nb+j]
    for (int i = tid; i < NCOL * DD; i += NTHR) {
        int j = i >> 10, k = i & 1023;
        Wsh[i] = W[(size_t)k * DD + nb + j];
        Ush[i] = U[(size_t)k * DD + nb + j];
    }
    // h_{-1} = 0 in slot 1 (step 0 reads slot (0+1)&1)
    {
        int b = tid >> 3, n = tid & 7;
        g_h[1][b * DD + nb + n] = 0.f;
    }
    __threadfence();
    __syncthreads();
    if (tid == 0) red_release_add(ctr);

    const int wid  = tid >> 5;   // column 0..7
    const int lane = tid & 31;   // batch 0..31
    const float bv = bias_l[nb + wid];

    for (int t = 0; t < SS; ++t) {
        wait_ge(ctr, (unsigned)NBLK * (unsigned)(t + 1));

        const float* xin = in + (size_t)t * in_st_t;
        const float* hin = g_h[(t + 1) & 1];

        float ax = 0.f, ah = 0.f;
#pragma unroll
        for (int kh = 0; kh < 2; ++kh) {
            // ---- stage half-panels: x[b][kh*512 .. +512) and h same ----
            for (int j = tid; j < BB * (HK / 4); j += NTHR) {
                int b = j >> 7, q = j & 127;                     // 128 float4 per row
                float4 xv = __ldg((const float4*)(xin + (size_t)b * in_st_b + kh * HK) + q);
                float4 hv = __ldcg((const float4*)(hin + (size_t)b * DD + kh * HK) + q);
                *(float4*)(xpan + b * XPAD + q * 4) = xv;
                *(float4*)(hpan + b * XPAD + q * 4) = hv;
            }
            __syncthreads();

            // ---- sequential ascending-k fma chains over this panel ----
            const float4* xr = (const float4*)(xpan + lane * XPAD);
            const float4* hr = (const float4*)(hpan + lane * XPAD);
            const float4* wr = (const float4*)(Wsh + wid * DD + kh * HK);
            const float4* ur = (const float4*)(Ush + wid * DD + kh * HK);
            float cax = 0.f, cah = 0.f;
#pragma unroll 4
            for (int q = 0; q < HK / 4; ++q) {
                const float4 xv = xr[q];
                const float4 wv = wr[q];
                const float4 hv = hr[q];
                const float4 uv = ur[q];
                cax = fmaf(xv.x, wv.x, cax);
                cah = fmaf(hv.x, uv.x, cah);
                cax = fmaf(xv.y, wv.y, cax);
                cah = fmaf(hv.y, uv.y, cah);
                cax = fmaf(xv.z, wv.z, cax);
                cah = fmaf(hv.z, uv.z, cah);
                cax = fmaf(xv.w, wv.w, cax);
                cah = fmaf(hv.w, uv.w, cah);
            }
            if (kh == 0) { ax = cax; ah = cah; }
            else         { ax = __fadd_rn(ax, cax); ah = __fadd_rn(ah, cah); }  // kc=512 join
            __syncthreads();   // panel consumed before next staging overwrites
        }

        const float pre = __fadd_rn(__fadd_rn(ax, ah), bv);   // (x@W + h@U) + b
        red[wid * 33 + lane] = xla_tanh_fma(pre);
        __syncthreads();

        // publish (coalesced remap): thread -> (b2, n2)
        {
            const int b2 = tid >> 3, n2 = tid & 7;
            const float v = red[n2 * 33 + b2];
            g_h[t & 1][b2 * DD + nb + n2] = v;
            outp[(size_t)t * out_st_t + (size_t)b2 * out_st_b + nb + n2] = v;
        }
        __threadfence();
        __syncthreads();
        if (tid == 0) red_release_add(ctr);
        __syncthreads();   // protect red[] and panels from next-iter overwrite
    }
}

extern "C" void kernel_launch(void* const* d_in, const int* in_sizes, int n_in,
                              void* d_out, int out_size) {
    const float* x    = (const float*)d_in[0];   // [32,512,1024]
    const float* wh   = (const float*)d_in[1];   // [2,1024,1024]
    const float* uh   = (const float*)d_in[2];   // [2,1024,1024]
    const float* bias = (const float*)d_in[3];   // [2,1024]
    float* out = (float*)d_out;                  // [32,512,1024]

    const int smem_bytes = (2 * NCOL * DD + 2 * BB * XPAD) * (int)sizeof(float); // 197632
    cudaFuncSetAttribute(rnn_layer, cudaFuncAttributeMaxDynamicSharedMemorySize, smem_bytes);

    float* h0all; cudaGetSymbolAddress((void**)&h0all, g_h0all);

    init_kernel<<<1, 1>>>();
    // layer 0: x native [B][S][D] -> h0all [S][B][D]
    rnn_layer<<<NBLK, NTHR, smem_bytes>>>(
        x, (size_t)DD, (size_t)SS * DD,
        wh, uh, bias,
        h0all, (size_t)BB * DD, (size_t)DD, 0);
    // layer 1: h0all [S][B][D] -> out native [B][S][D]
    rnn_layer<<<NBLK, NTHR, smem_bytes>>>(
        h0all, (size_t)BB * DD, (size_t)DD,
        wh + DD * DD, uh + DD * DD, bias + DD,
        out, (size_t)DD, (size_t)SS * DD, 1);
}